// round 1
// baseline (speedup 1.0000x reference)
#include <cuda_runtime.h>
#include <math.h>

#define BATCH 16
#define NPTS  2048

// ---------------- scratch (device globals; no runtime allocation) ----------------
__device__ float g_h21 [(size_t)BATCH*21*NPTS];
__device__ float g_h128[(size_t)BATCH*128*NPTS];
__device__ float g_h256[(size_t)BATCH*256*NPTS];
__device__ float g_gm  [BATCH*256];
__device__ float g_hcat[(size_t)BATCH*512*NPTS];
__device__ float g_h   [(size_t)BATCH*512*NPTS];
__device__ float g_qk  [(size_t)BATCH*128*NPTS];
__device__ float g_xv  [(size_t)BATCH*512*NPTS];
__device__ float g_attn[(size_t)BATCH*NPTS*NPTS];   // 256 MB
__device__ float g_cs  [BATCH*NPTS];
__device__ float g_xr  [(size_t)BATCH*512*NPTS];
__device__ float g_dd  [(size_t)BATCH*512*NPTS];
__device__ float g_mu  [512];
__device__ float g_rs  [512];
__device__ float g_h2  [(size_t)BATCH*512*NPTS];
__device__ float g_opre[(size_t)BATCH*1024*NPTS];   // 128 MB

// ---------------- generic strided batched SGEMM ----------------
// C[b][m][n] (row-major, ld=N) = sum_k A(m,k) * B(k,n) (+bias[m]) (+relu)
// A element: Ab + m*sa_m + k*sa_k ; B element: Bb + k*sb_k + n*sb_n
#define BM 128
#define BN 64
#define BK 16

__global__ __launch_bounds__(256)
void gemm_k(const float* __restrict__ A, const float* __restrict__ B,
            const float* __restrict__ bias, float* __restrict__ C,
            int M, int N, int K,
            long sa_m, long sa_k, long a_bat,
            long sb_k, long sb_n, long b_bat,
            long c_bat, int relu)
{
    __shared__ __align__(16) float As[BK][BM+4];
    __shared__ __align__(16) float Bs[BK][BN+4];
    const float* Ab = A + (long)blockIdx.z * a_bat;
    const float* Bb = B + (long)blockIdx.z * b_bat;
    float*       Cb = C + (long)blockIdx.z * c_bat;
    int bm = blockIdx.y * BM, bn = blockIdx.x * BN;
    int tid = threadIdx.x;
    int tx = tid & 15, ty = tid >> 4;

    float acc[8][4];
#pragma unroll
    for (int i = 0; i < 8; i++)
#pragma unroll
        for (int j = 0; j < 4; j++) acc[i][j] = 0.f;

    const bool a_unit_k = (sa_k == 1);
    const bool b_unit_n = (sb_n == 1);

    for (int k0 = 0; k0 < K; k0 += BK) {
        if (a_unit_k) {
#pragma unroll
            for (int i = 0; i < 8; i++) {
                int idx = tid + i*256;
                int kk = idx & 15, mm = idx >> 4;
                int kg = k0 + kk;
                As[kk][mm] = (kg < K) ? Ab[(long)(bm+mm)*sa_m + kg] : 0.f;
            }
        } else {
#pragma unroll
            for (int i = 0; i < 8; i++) {
                int idx = tid + i*256;
                int mm = idx & 127, kk = idx >> 7;
                int kg = k0 + kk;
                As[kk][mm] = (kg < K) ? Ab[(long)(bm+mm)*sa_m + (long)kg*sa_k] : 0.f;
            }
        }
        if (b_unit_n) {
#pragma unroll
            for (int i = 0; i < 4; i++) {
                int idx = tid + i*256;
                int nn = idx & 63, kk = idx >> 6;
                int kg = k0 + kk;
                Bs[kk][nn] = (kg < K) ? Bb[(long)kg*sb_k + (bn+nn)] : 0.f;
            }
        } else {
#pragma unroll
            for (int i = 0; i < 4; i++) {
                int idx = tid + i*256;
                int kk = idx & 15, nn = idx >> 4;
                int kg = k0 + kk;
                Bs[kk][nn] = (kg < K) ? Bb[(long)kg*sb_k + (long)(bn+nn)*sb_n] : 0.f;
            }
        }
        __syncthreads();
#pragma unroll
        for (int kk = 0; kk < BK; kk++) {
            float4 a0 = *(const float4*)&As[kk][ty*8];
            float4 a1 = *(const float4*)&As[kk][ty*8+4];
            float4 b0 = *(const float4*)&Bs[kk][tx*4];
            float a[8] = {a0.x,a0.y,a0.z,a0.w,a1.x,a1.y,a1.z,a1.w};
            float bv[4] = {b0.x,b0.y,b0.z,b0.w};
#pragma unroll
            for (int i = 0; i < 8; i++)
#pragma unroll
                for (int j = 0; j < 4; j++)
                    acc[i][j] = fmaf(a[i], bv[j], acc[i][j]);
        }
        __syncthreads();
    }
#pragma unroll
    for (int i = 0; i < 8; i++) {
        int mg = bm + ty*8 + i;
        float bb = bias ? bias[mg] : 0.f;
        float4 v;
        v.x = acc[i][0] + bb; v.y = acc[i][1] + bb;
        v.z = acc[i][2] + bb; v.w = acc[i][3] + bb;
        if (relu) {
            v.x = fmaxf(v.x, 0.f); v.y = fmaxf(v.y, 0.f);
            v.z = fmaxf(v.z, 0.f); v.w = fmaxf(v.w, 0.f);
        }
        *(float4*)&Cb[(long)mg*N + bn + tx*4] = v;
    }
}

// ---------------- positional encoding ----------------
__global__ void posenc_k(const float* __restrict__ x, float* __restrict__ h21)
{
    int idx = blockIdx.x*blockDim.x + threadIdx.x;
    if (idx >= BATCH*3*NPTS) return;
    int n = idx % NPTS; int r = idx / NPTS;
    int dim = r % 3, b = r / 3;
    float t = x[((long)b*3 + dim)*NPTS + n];
    float* o = h21 + (long)b*21*NPTS + n;
    o[(long)(dim     )*NPTS] = t;
    o[(long)(3  + dim)*NPTS] = sinf(t);
    o[(long)(6  + dim)*NPTS] = cosf(t);
    o[(long)(9  + dim)*NPTS] = sinf(2.f*t);
    o[(long)(12 + dim)*NPTS] = cosf(2.f*t);
    o[(long)(15 + dim)*NPTS] = sinf(4.f*t);
    o[(long)(18 + dim)*NPTS] = cosf(4.f*t);
}

// ---------------- row max over NPTS contiguous elements ----------------
__global__ void rowmax_k(const float* __restrict__ in, float* __restrict__ out)
{
    int r = blockIdx.x;
    const float* p = in + (long)r*NPTS;
    float m = -3.402823466e38f;
    for (int i = threadIdx.x; i < NPTS; i += 256) m = fmaxf(m, p[i]);
    __shared__ float sh[8];
#pragma unroll
    for (int o = 16; o > 0; o >>= 1) m = fmaxf(m, __shfl_xor_sync(0xffffffffu, m, o));
    if ((threadIdx.x & 31) == 0) sh[threadIdx.x >> 5] = m;
    __syncthreads();
    if (threadIdx.x == 0) {
        float v = sh[0];
#pragma unroll
        for (int i = 1; i < 8; i++) v = fmaxf(v, sh[i]);
        out[r] = v;
    }
}

// ---------------- concat [h256 ; broadcast gmax] -> [B,512,N] ----------------
__global__ void concat_k(const float* __restrict__ h256, const float* __restrict__ gm,
                         float* __restrict__ hcat)
{
    long idx = (long)blockIdx.x*blockDim.x + threadIdx.x;
    if (idx >= (long)BATCH*512*NPTS) return;
    int n = idx % NPTS;
    int c = (idx / NPTS) % 512;
    int b = idx / ((long)512*NPTS);
    hcat[idx] = (c < 256) ? h256[((long)b*256 + c)*NPTS + n] : gm[b*256 + (c - 256)];
}

// ---------------- softmax over last dim (rows of attn), in place ----------------
__global__ void softmax_k(float* __restrict__ attn)
{
    size_t row = blockIdx.x;                // b*NPTS + q
    float* p = attn + row * (size_t)NPTS;
    int t = threadIdx.x;
    float v[8];
    float m = -3.402823466e38f;
#pragma unroll
    for (int i = 0; i < 8; i++) { v[i] = p[t + 256*i]; m = fmaxf(m, v[i]); }
    __shared__ float sh[8];
#pragma unroll
    for (int o = 16; o > 0; o >>= 1) m = fmaxf(m, __shfl_xor_sync(0xffffffffu, m, o));
    if ((t & 31) == 0) sh[t >> 5] = m;
    __syncthreads();
    float rm = sh[0];
#pragma unroll
    for (int i = 1; i < 8; i++) rm = fmaxf(rm, sh[i]);
    __syncthreads();
    float s = 0.f;
#pragma unroll
    for (int i = 0; i < 8; i++) { v[i] = expf(v[i] - rm); s += v[i]; }
#pragma unroll
    for (int o = 16; o > 0; o >>= 1) s += __shfl_xor_sync(0xffffffffu, s, o);
    if ((t & 31) == 0) sh[t >> 5] = s;
    __syncthreads();
    float rs = 0.f;
#pragma unroll
    for (int i = 0; i < 8; i++) rs += sh[i];
    float inv = 1.f / rs;
#pragma unroll
    for (int i = 0; i < 8; i++) p[t + 256*i] = v[i] * inv;
}

// ---------------- column sums over q (per b,k) ----------------
__global__ void colsum_k(const float* __restrict__ attn, float* __restrict__ cs)
{
    int k = blockIdx.x*256 + threadIdx.x;
    int b = blockIdx.y;
    const float* p = attn + (size_t)b*NPTS*NPTS + k;
    float s = 0.f;
#pragma unroll 8
    for (int q = 0; q < NPTS; q++) s += p[(size_t)q*NPTS];
    cs[b*NPTS + k] = s;
}

// ---------------- fold double-normalization into xv columns ----------------
__global__ void scalexv_k(float* __restrict__ xv, const float* __restrict__ cs)
{
    long idx = (long)blockIdx.x*blockDim.x + threadIdx.x;
    if (idx >= (long)BATCH*512*NPTS) return;
    int k = idx % NPTS;
    int b = idx / ((long)512*NPTS);
    xv[idx] *= 1.f / (1e-9f + cs[b*NPTS + k]);
}

// ---------------- xr = h - xr (in place) ----------------
__global__ void sub_k(const float* __restrict__ h, float* __restrict__ xr)
{
    long idx = (long)blockIdx.x*blockDim.x + threadIdx.x;
    if (idx >= (long)BATCH*512*NPTS) return;
    xr[idx] = h[idx] - xr[idx];
}

// ---------------- BN batch stats per channel ----------------
__global__ void bnstats_k(const float* __restrict__ d)
{
    int c = blockIdx.x;
    int t = threadIdx.x;
    double s = 0.0, s2 = 0.0;
    for (int i = t; i < BATCH*NPTS; i += 256) {
        int b = i / NPTS, n = i % NPTS;
        float v = d[((long)b*512 + c)*NPTS + n];
        s += v; s2 += (double)v*v;
    }
    __shared__ double sh[256], sh2[256];
    sh[t] = s; sh2[t] = s2; __syncthreads();
    for (int o = 128; o > 0; o >>= 1) {
        if (t < o) { sh[t] += sh[t+o]; sh2[t] += sh2[t+o]; }
        __syncthreads();
    }
    if (t == 0) {
        double mu  = sh[0]  / (double)(BATCH*NPTS);
        double var = sh2[0] / (double)(BATCH*NPTS) - mu*mu;
        g_mu[c] = (float)mu;
        g_rs[c] = (float)(1.0 / sqrt(var + 1e-5));
    }
}

// ---------------- h2 = h + relu(gamma*(d-mu)*rsig + beta) ----------------
__global__ void bnapply_k(const float* __restrict__ h, const float* __restrict__ d,
                          const float* __restrict__ gamma, const float* __restrict__ beta,
                          float* __restrict__ h2)
{
    long idx = (long)blockIdx.x*blockDim.x + threadIdx.x;
    if (idx >= (long)BATCH*512*NPTS) return;
    int c = (idx / NPTS) % 512;
    float v = gamma[c] * (d[idx] - g_mu[c]) * g_rs[c] + beta[c];
    h2[idx] = h[idx] + fmaxf(v, 0.f);
}

// ---------------- launch ----------------
extern "C" void kernel_launch(void* const* d_in, const int* in_sizes, int n_in,
                              void* d_out, int out_size)
{
    const float* x    = (const float*)d_in[0];
    const float* w1   = (const float*)d_in[1];
    const float* b1   = (const float*)d_in[2];
    const float* w2   = (const float*)d_in[3];
    const float* b2   = (const float*)d_in[4];
    const float* w3   = (const float*)d_in[5];
    const float* b3   = (const float*)d_in[6];
    const float* w4   = (const float*)d_in[7];
    const float* b4   = (const float*)d_in[8];
    const float* wqk  = (const float*)d_in[9];
    const float* wv   = (const float*)d_in[10];
    const float* bv   = (const float*)d_in[11];
    const float* wt   = (const float*)d_in[12];
    const float* bt   = (const float*)d_in[13];
    const float* gamma= (const float*)d_in[14];
    const float* beta = (const float*)d_in[15];
    float* out = (float*)d_out;

    float *h21,*h128,*h256,*gm,*hcat,*h,*qk,*xv,*attn,*cs,*xr,*dd,*h2,*opre;
    cudaGetSymbolAddress((void**)&h21,  g_h21);
    cudaGetSymbolAddress((void**)&h128, g_h128);
    cudaGetSymbolAddress((void**)&h256, g_h256);
    cudaGetSymbolAddress((void**)&gm,   g_gm);
    cudaGetSymbolAddress((void**)&hcat, g_hcat);
    cudaGetSymbolAddress((void**)&h,    g_h);
    cudaGetSymbolAddress((void**)&qk,   g_qk);
    cudaGetSymbolAddress((void**)&xv,   g_xv);
    cudaGetSymbolAddress((void**)&attn, g_attn);
    cudaGetSymbolAddress((void**)&cs,   g_cs);
    cudaGetSymbolAddress((void**)&xr,   g_xr);
    cudaGetSymbolAddress((void**)&dd,   g_dd);
    cudaGetSymbolAddress((void**)&h2,   g_h2);
    cudaGetSymbolAddress((void**)&opre, g_opre);

    const long EW = (long)BATCH*512*NPTS;

    // positional encoding -> [B,21,N]
    posenc_k<<<(BATCH*3*NPTS + 255)/256, 256>>>(x, h21);

    // conv1 (21->128) + relu
    gemm_k<<<dim3(32,1,BATCH),256>>>(w1, h21, b1, h128, 128, NPTS, 21,
        21, 1, 0,   (long)NPTS, 1, (long)21*NPTS,   (long)128*NPTS, 1);
    // conv2 (128->256)
    gemm_k<<<dim3(32,2,BATCH),256>>>(w2, h128, b2, h256, 256, NPTS, 128,
        128, 1, 0,  (long)NPTS, 1, (long)128*NPTS,  (long)256*NPTS, 0);
    // global max over N -> [B,256]
    rowmax_k<<<BATCH*256, 256>>>(h256, gm);
    // concat -> [B,512,N]
    concat_k<<<(int)((EW + 255)/256), 256>>>(h256, gm, hcat);
    // conv3 (512->512) + relu -> h
    gemm_k<<<dim3(32,4,BATCH),256>>>(w3, hcat, b3, h, 512, NPTS, 512,
        512, 1, 0,  (long)NPTS, 1, (long)512*NPTS,  (long)512*NPTS, 1);
    // q/k projection (tied weights, computed once): [B,128,N]
    gemm_k<<<dim3(32,1,BATCH),256>>>(wqk, h, nullptr, qk, 128, NPTS, 512,
        512, 1, 0,  (long)NPTS, 1, (long)512*NPTS,  (long)128*NPTS, 0);
    // v projection
    gemm_k<<<dim3(32,4,BATCH),256>>>(wv, h, bv, xv, 512, NPTS, 512,
        512, 1, 0,  (long)NPTS, 1, (long)512*NPTS,  (long)512*NPTS, 0);
    // energy = qk^T * qk  -> attn [B,N,N]
    gemm_k<<<dim3(32,16,BATCH),256>>>(qk, qk, nullptr, attn, NPTS, NPTS, 128,
        1, (long)NPTS, (long)128*NPTS,   (long)NPTS, 1, (long)128*NPTS,
        (long)NPTS*NPTS, 0);
    // softmax over k (rows)
    softmax_k<<<BATCH*NPTS, 256>>>(attn);
    // column sums over q
    colsum_k<<<dim3(NPTS/256, BATCH), 256>>>(attn, cs);
    // fold 1/(1e-9+colsum) into xv columns
    scalexv_k<<<(int)((EW + 255)/256), 256>>>(xv, cs);
    // x_r = xv_scaled @ attn^T : [B,512,N]
    gemm_k<<<dim3(32,4,BATCH),256>>>(xv, attn, nullptr, xr, 512, NPTS, NPTS,
        (long)NPTS, 1, (long)512*NPTS,   1, (long)NPTS, (long)NPTS*NPTS,
        (long)512*NPTS, 0);
    // xr = h - xr
    sub_k<<<(int)((EW + 255)/256), 256>>>(h, xr);
    // trans conv: d = wt @ (h - xr) + bt
    gemm_k<<<dim3(32,4,BATCH),256>>>(wt, xr, bt, dd, 512, NPTS, 512,
        512, 1, 0,  (long)NPTS, 1, (long)512*NPTS,  (long)512*NPTS, 0);
    // batch-norm (training-mode batch stats) + relu + residual
    bnstats_k<<<512, 256>>>(dd);
    bnapply_k<<<(int)((EW + 255)/256), 256>>>(h, dd, gamma, beta, h2);
    // conv4 (512->1024)
    gemm_k<<<dim3(32,8,BATCH),256>>>(w4, h2, b4, opre, 1024, NPTS, 512,
        512, 1, 0,  (long)NPTS, 1, (long)512*NPTS,  (long)1024*NPTS, 0);
    // final max over N -> [B,1024]
    rowmax_k<<<BATCH*1024, 256>>>(opre, out);
}

// round 2
// speedup vs baseline: 3.2079x; 3.2079x over previous
#include <cuda_runtime.h>
#include <math.h>
#include <stdint.h>

#define BATCH 16
#define NPTS  2048

// ---------------- scratch (device globals; no runtime allocation) ----------------
__device__ float g_h21 [(size_t)BATCH*21*NPTS];
__device__ float g_h128[(size_t)BATCH*128*NPTS];
__device__ float g_h256[(size_t)BATCH*256*NPTS];
__device__ float g_gm  [BATCH*256];
__device__ float g_hcat[(size_t)BATCH*512*NPTS];
__device__ float g_h   [(size_t)BATCH*512*NPTS];
__device__ float g_qk  [(size_t)BATCH*128*NPTS];
__device__ float g_xv  [(size_t)BATCH*512*NPTS];
__device__ float g_attn[(size_t)BATCH*NPTS*NPTS];   // 256 MB
__device__ float g_cs  [BATCH*NPTS];
__device__ float g_xr  [(size_t)BATCH*512*NPTS];
__device__ float g_dd  [(size_t)BATCH*512*NPTS];
__device__ float g_mu  [512];
__device__ float g_rs  [512];
__device__ float g_h2  [(size_t)BATCH*512*NPTS];
__device__ float g_opre[(size_t)BATCH*1024*NPTS];   // 128 MB

// ---------------- TF32 tensor-core strided batched GEMM ----------------
// C[b][m][n] (row-major, ld=N) = sum_k A(m,k)*B(k,n) (+bias[m]) (+relu)
// A(m,k) = Ab[m*sa_m + k*sa_k]; requires sa_m==1 (direct) or sa_k==1 (transpose-load)
// B(k,n) = Bb[k*sb_k + n*sb_n]; requires sb_n==1 (direct) or sb_k==1 (transpose-load)
#define BM 128
#define BN 128
#define BKT 16

__device__ __forceinline__ uint32_t f2tf(float f){
    uint32_t u;
    asm("cvt.rna.tf32.f32 %0, %1;" : "=r"(u) : "f"(f));
    return u;
}

__device__ __forceinline__ void mma_tf32(float c[4], uint32_t a0, uint32_t a1,
                                         uint32_t a2, uint32_t a3,
                                         uint32_t b0, uint32_t b1){
    asm volatile(
        "mma.sync.aligned.m16n8k8.row.col.f32.tf32.tf32.f32 "
        "{%0,%1,%2,%3}, {%4,%5,%6,%7}, {%8,%9}, {%0,%1,%2,%3};"
        : "+f"(c[0]), "+f"(c[1]), "+f"(c[2]), "+f"(c[3])
        : "r"(a0), "r"(a1), "r"(a2), "r"(a3), "r"(b0), "r"(b1));
}

__global__ __launch_bounds__(256)
void mm_tf32_k(const float* __restrict__ A, const float* __restrict__ B,
               const float* __restrict__ bias, float* __restrict__ C,
               int M, int N, int K,
               long sa_m, long sa_k, long a_bat,
               long sb_k, long sb_n, long b_bat,
               long c_bat, int relu)
{
    __shared__ __align__(16) uint32_t As[2][BKT][BM+8];
    __shared__ __align__(16) uint32_t Bs[2][BKT][BN+8];
    const float* Ab = A + (long)blockIdx.z * a_bat;
    const float* Bb = B + (long)blockIdx.z * b_bat;
    float*       Cb = C + (long)blockIdx.z * c_bat;
    const int bm = blockIdx.y * BM, bn = blockIdx.x * BN;
    const int tid = threadIdx.x;
    const int lane = tid & 31, wid = tid >> 5;
    const int wm = wid >> 2, wn = wid & 3;      // warp tile origin (wm*64, wn*32)
    const int grp = lane >> 2, tig = lane & 3;

    const bool aT = (sa_k == 1);                // global A is k-contiguous -> transpose into As[k][m]
    const bool bT = (sb_n != 1);                // global B is k-contiguous -> transpose into Bs[k][n]
    const bool aVec = aT && ((sa_m & 3) == 0) && ((K & 3) == 0);
    const bool bVec = bT && ((sb_n & 3) == 0) && ((K & 3) == 0);

    float acc[4][4][4];
#pragma unroll
    for (int i = 0; i < 4; i++)
#pragma unroll
        for (int j = 0; j < 4; j++)
#pragma unroll
            for (int r = 0; r < 4; r++) acc[i][j][r] = 0.f;

    float ra[8], rb[8];

    auto ldgA = [&](int k0){
        if (!aT) {
#pragma unroll
            for (int i = 0; i < 2; i++) {
                int idx = tid + i*256;
                int kk = idx >> 5, mm = (idx & 31) << 2;
                int kg = k0 + kk;
                float4 v = make_float4(0.f,0.f,0.f,0.f);
                if (kg < K) v = *(const float4*)(Ab + (long)kg*sa_k + (bm + mm));
                ra[i*4+0]=v.x; ra[i*4+1]=v.y; ra[i*4+2]=v.z; ra[i*4+3]=v.w;
            }
        } else {
#pragma unroll
            for (int i = 0; i < 2; i++) {
                int idx = tid + i*256;
                int mm = idx >> 2, kq = (idx & 3) << 2;
                int kg = k0 + kq;
                const float* p = Ab + (long)(bm + mm)*sa_m + kg;
                if (aVec) {
                    float4 v = make_float4(0.f,0.f,0.f,0.f);
                    if (kg < K) v = *(const float4*)p;
                    ra[i*4+0]=v.x; ra[i*4+1]=v.y; ra[i*4+2]=v.z; ra[i*4+3]=v.w;
                } else {
#pragma unroll
                    for (int j = 0; j < 4; j++)
                        ra[i*4+j] = (kg + j < K) ? p[j] : 0.f;
                }
            }
        }
    };
    auto stsA = [&](int buf){
        if (!aT) {
#pragma unroll
            for (int i = 0; i < 2; i++) {
                int idx = tid + i*256;
                int kk = idx >> 5, mm = (idx & 31) << 2;
                uint4 u; u.x=f2tf(ra[i*4+0]); u.y=f2tf(ra[i*4+1]);
                         u.z=f2tf(ra[i*4+2]); u.w=f2tf(ra[i*4+3]);
                *(uint4*)&As[buf][kk][mm] = u;
            }
        } else {
#pragma unroll
            for (int i = 0; i < 2; i++) {
                int idx = tid + i*256;
                int mm = idx >> 2, kq = (idx & 3) << 2;
#pragma unroll
                for (int j = 0; j < 4; j++)
                    As[buf][kq+j][mm] = f2tf(ra[i*4+j]);
            }
        }
    };
    auto ldgB = [&](int k0){
        if (!bT) {
#pragma unroll
            for (int i = 0; i < 2; i++) {
                int idx = tid + i*256;
                int kk = idx >> 5, nn = (idx & 31) << 2;
                int kg = k0 + kk;
                float4 v = make_float4(0.f,0.f,0.f,0.f);
                if (kg < K) v = *(const float4*)(Bb + (long)kg*sb_k + (bn + nn));
                rb[i*4+0]=v.x; rb[i*4+1]=v.y; rb[i*4+2]=v.z; rb[i*4+3]=v.w;
            }
        } else {
#pragma unroll
            for (int i = 0; i < 2; i++) {
                int idx = tid + i*256;
                int nn = idx >> 2, kq = (idx & 3) << 2;
                int kg = k0 + kq;
                const float* p = Bb + (long)(bn + nn)*sb_n + kg;
                if (bVec) {
                    float4 v = make_float4(0.f,0.f,0.f,0.f);
                    if (kg < K) v = *(const float4*)p;
                    rb[i*4+0]=v.x; rb[i*4+1]=v.y; rb[i*4+2]=v.z; rb[i*4+3]=v.w;
                } else {
#pragma unroll
                    for (int j = 0; j < 4; j++)
                        rb[i*4+j] = (kg + j < K) ? p[j] : 0.f;
                }
            }
        }
    };
    auto stsB = [&](int buf){
        if (!bT) {
#pragma unroll
            for (int i = 0; i < 2; i++) {
                int idx = tid + i*256;
                int kk = idx >> 5, nn = (idx & 31) << 2;
                uint4 u; u.x=f2tf(rb[i*4+0]); u.y=f2tf(rb[i*4+1]);
                         u.z=f2tf(rb[i*4+2]); u.w=f2tf(rb[i*4+3]);
                *(uint4*)&Bs[buf][kk][nn] = u;
            }
        } else {
#pragma unroll
            for (int i = 0; i < 2; i++) {
                int idx = tid + i*256;
                int nn = idx >> 2, kq = (idx & 3) << 2;
#pragma unroll
                for (int j = 0; j < 4; j++)
                    Bs[buf][kq+j][nn] = f2tf(rb[i*4+j]);
            }
        }
    };

    const int ntiles = (K + BKT - 1) / BKT;
    int p = 0;
    ldgA(0); ldgB(0);
    stsA(0); stsB(0);
    __syncthreads();

    for (int it = 0; it < ntiles; it++) {
        if (it + 1 < ntiles) { ldgA((it+1)*BKT); ldgB((it+1)*BKT); }
#pragma unroll
        for (int ks = 0; ks < 2; ks++) {
            const int kb = ks * 8;
            uint32_t af[4][4], bf[4][2];
#pragma unroll
            for (int i = 0; i < 4; i++) {
                int m0 = wm*64 + i*16 + grp;
                af[i][0] = As[p][kb+tig  ][m0  ];
                af[i][1] = As[p][kb+tig  ][m0+8];
                af[i][2] = As[p][kb+tig+4][m0  ];
                af[i][3] = As[p][kb+tig+4][m0+8];
            }
#pragma unroll
            for (int j = 0; j < 4; j++) {
                int n0 = wn*32 + j*8 + grp;
                bf[j][0] = Bs[p][kb+tig  ][n0];
                bf[j][1] = Bs[p][kb+tig+4][n0];
            }
#pragma unroll
            for (int i = 0; i < 4; i++)
#pragma unroll
                for (int j = 0; j < 4; j++)
                    mma_tf32(acc[i][j], af[i][0], af[i][1], af[i][2], af[i][3],
                             bf[j][0], bf[j][1]);
        }
        if (it + 1 < ntiles) {
            stsA(1-p); stsB(1-p);
            __syncthreads();
            p ^= 1;
        }
    }

#pragma unroll
    for (int i = 0; i < 4; i++) {
        int mg = bm + wm*64 + i*16 + grp;
        float bi0 = bias ? bias[mg]   : 0.f;
        float bi1 = bias ? bias[mg+8] : 0.f;
#pragma unroll
        for (int j = 0; j < 4; j++) {
            int ng = bn + wn*32 + j*8 + tig*2;
            float2 v0, v1;
            v0.x = acc[i][j][0] + bi0; v0.y = acc[i][j][1] + bi0;
            v1.x = acc[i][j][2] + bi1; v1.y = acc[i][j][3] + bi1;
            if (relu) {
                v0.x = fmaxf(v0.x, 0.f); v0.y = fmaxf(v0.y, 0.f);
                v1.x = fmaxf(v1.x, 0.f); v1.y = fmaxf(v1.y, 0.f);
            }
            *(float2*)&Cb[(long)mg*N + ng]     = v0;
            *(float2*)&Cb[(long)(mg+8)*N + ng] = v1;
        }
    }
}

// ---------------- positional encoding ----------------
__global__ void posenc_k(const float* __restrict__ x, float* __restrict__ h21)
{
    int idx = blockIdx.x*blockDim.x + threadIdx.x;
    if (idx >= BATCH*3*NPTS) return;
    int n = idx % NPTS; int r = idx / NPTS;
    int dim = r % 3, b = r / 3;
    float t = x[((long)b*3 + dim)*NPTS + n];
    float* o = h21 + (long)b*21*NPTS + n;
    o[(long)(dim     )*NPTS] = t;
    o[(long)(3  + dim)*NPTS] = sinf(t);
    o[(long)(6  + dim)*NPTS] = cosf(t);
    o[(long)(9  + dim)*NPTS] = sinf(2.f*t);
    o[(long)(12 + dim)*NPTS] = cosf(2.f*t);
    o[(long)(15 + dim)*NPTS] = sinf(4.f*t);
    o[(long)(18 + dim)*NPTS] = cosf(4.f*t);
}

// ---------------- row max over NPTS contiguous elements ----------------
__global__ void rowmax_k(const float* __restrict__ in, float* __restrict__ out)
{
    int r = blockIdx.x;
    const float* p = in + (long)r*NPTS;
    float m = -3.402823466e38f;
    for (int i = threadIdx.x; i < NPTS; i += 256) m = fmaxf(m, p[i]);
    __shared__ float sh[8];
#pragma unroll
    for (int o = 16; o > 0; o >>= 1) m = fmaxf(m, __shfl_xor_sync(0xffffffffu, m, o));
    if ((threadIdx.x & 31) == 0) sh[threadIdx.x >> 5] = m;
    __syncthreads();
    if (threadIdx.x == 0) {
        float v = sh[0];
#pragma unroll
        for (int i = 1; i < 8; i++) v = fmaxf(v, sh[i]);
        out[r] = v;
    }
}

// ---------------- concat [h256 ; broadcast gmax] -> [B,512,N] ----------------
__global__ void concat_k(const float* __restrict__ h256, const float* __restrict__ gm,
                         float* __restrict__ hcat)
{
    long idx = (long)blockIdx.x*blockDim.x + threadIdx.x;
    if (idx >= (long)BATCH*512*NPTS) return;
    int n = idx % NPTS;
    int c = (idx / NPTS) % 512;
    int b = idx / ((long)512*NPTS);
    hcat[idx] = (c < 256) ? h256[((long)b*256 + c)*NPTS + n] : gm[b*256 + (c - 256)];
}

// ---------------- softmax over last dim (rows of attn), in place ----------------
__global__ void softmax_k(float* __restrict__ attn)
{
    size_t row = blockIdx.x;                // b*NPTS + q
    float* p = attn + row * (size_t)NPTS;
    int t = threadIdx.x;
    float v[8];
    float m = -3.402823466e38f;
#pragma unroll
    for (int i = 0; i < 8; i++) { v[i] = p[t + 256*i]; m = fmaxf(m, v[i]); }
    __shared__ float sh[8];
#pragma unroll
    for (int o = 16; o > 0; o >>= 1) m = fmaxf(m, __shfl_xor_sync(0xffffffffu, m, o));
    if ((t & 31) == 0) sh[t >> 5] = m;
    __syncthreads();
    float rm = sh[0];
#pragma unroll
    for (int i = 1; i < 8; i++) rm = fmaxf(rm, sh[i]);
    __syncthreads();
    float s = 0.f;
#pragma unroll
    for (int i = 0; i < 8; i++) { v[i] = expf(v[i] - rm); s += v[i]; }
#pragma unroll
    for (int o = 16; o > 0; o >>= 1) s += __shfl_xor_sync(0xffffffffu, s, o);
    if ((t & 31) == 0) sh[t >> 5] = s;
    __syncthreads();
    float rs = 0.f;
#pragma unroll
    for (int i = 0; i < 8; i++) rs += sh[i];
    float inv = 1.f / rs;
#pragma unroll
    for (int i = 0; i < 8; i++) p[t + 256*i] = v[i] * inv;
}

// ---------------- column sums over q (per b,k) ----------------
__global__ void colsum_k(const float* __restrict__ attn, float* __restrict__ cs)
{
    int k = blockIdx.x*256 + threadIdx.x;
    int b = blockIdx.y;
    const float* p = attn + (size_t)b*NPTS*NPTS + k;
    float s = 0.f;
#pragma unroll 8
    for (int q = 0; q < NPTS; q++) s += p[(size_t)q*NPTS];
    cs[b*NPTS + k] = s;
}

// ---------------- fold double-normalization into xv columns ----------------
__global__ void scalexv_k(float* __restrict__ xv, const float* __restrict__ cs)
{
    long idx = (long)blockIdx.x*blockDim.x + threadIdx.x;
    if (idx >= (long)BATCH*512*NPTS) return;
    int k = idx % NPTS;
    int b = idx / ((long)512*NPTS);
    xv[idx] *= 1.f / (1e-9f + cs[b*NPTS + k]);
}

// ---------------- xr = h - xr (in place) ----------------
__global__ void sub_k(const float* __restrict__ h, float* __restrict__ xr)
{
    long idx = (long)blockIdx.x*blockDim.x + threadIdx.x;
    if (idx >= (long)BATCH*512*NPTS) return;
    xr[idx] = h[idx] - xr[idx];
}

// ---------------- BN batch stats per channel ----------------
__global__ void bnstats_k(const float* __restrict__ d)
{
    int c = blockIdx.x;
    int t = threadIdx.x;
    double s = 0.0, s2 = 0.0;
    for (int i = t; i < BATCH*NPTS; i += 256) {
        int b = i / NPTS, n = i % NPTS;
        float v = d[((long)b*512 + c)*NPTS + n];
        s += v; s2 += (double)v*v;
    }
    __shared__ double sh[256], sh2[256];
    sh[t] = s; sh2[t] = s2; __syncthreads();
    for (int o = 128; o > 0; o >>= 1) {
        if (t < o) { sh[t] += sh[t+o]; sh2[t] += sh2[t+o]; }
        __syncthreads();
    }
    if (t == 0) {
        double mu  = sh[0]  / (double)(BATCH*NPTS);
        double var = sh2[0] / (double)(BATCH*NPTS) - mu*mu;
        g_mu[c] = (float)mu;
        g_rs[c] = (float)(1.0 / sqrt(var + 1e-5));
    }
}

// ---------------- h2 = h + relu(gamma*(d-mu)*rsig + beta) ----------------
__global__ void bnapply_k(const float* __restrict__ h, const float* __restrict__ d,
                          const float* __restrict__ gamma, const float* __restrict__ beta,
                          float* __restrict__ h2)
{
    long idx = (long)blockIdx.x*blockDim.x + threadIdx.x;
    if (idx >= (long)BATCH*512*NPTS) return;
    int c = (idx / NPTS) % 512;
    float v = gamma[c] * (d[idx] - g_mu[c]) * g_rs[c] + beta[c];
    h2[idx] = h[idx] + fmaxf(v, 0.f);
}

// ---------------- launch ----------------
extern "C" void kernel_launch(void* const* d_in, const int* in_sizes, int n_in,
                              void* d_out, int out_size)
{
    const float* x    = (const float*)d_in[0];
    const float* w1   = (const float*)d_in[1];
    const float* b1   = (const float*)d_in[2];
    const float* w2   = (const float*)d_in[3];
    const float* b2   = (const float*)d_in[4];
    const float* w3   = (const float*)d_in[5];
    const float* b3   = (const float*)d_in[6];
    const float* w4   = (const float*)d_in[7];
    const float* b4   = (const float*)d_in[8];
    const float* wqk  = (const float*)d_in[9];
    const float* wv   = (const float*)d_in[10];
    const float* bv   = (const float*)d_in[11];
    const float* wt   = (const float*)d_in[12];
    const float* bt   = (const float*)d_in[13];
    const float* gamma= (const float*)d_in[14];
    const float* beta = (const float*)d_in[15];
    float* out = (float*)d_out;

    float *h21,*h128,*h256,*gm,*hcat,*h,*qk,*xv,*attn,*cs,*xr,*dd,*h2,*opre;
    cudaGetSymbolAddress((void**)&h21,  g_h21);
    cudaGetSymbolAddress((void**)&h128, g_h128);
    cudaGetSymbolAddress((void**)&h256, g_h256);
    cudaGetSymbolAddress((void**)&gm,   g_gm);
    cudaGetSymbolAddress((void**)&hcat, g_hcat);
    cudaGetSymbolAddress((void**)&h,    g_h);
    cudaGetSymbolAddress((void**)&qk,   g_qk);
    cudaGetSymbolAddress((void**)&xv,   g_xv);
    cudaGetSymbolAddress((void**)&attn, g_attn);
    cudaGetSymbolAddress((void**)&cs,   g_cs);
    cudaGetSymbolAddress((void**)&xr,   g_xr);
    cudaGetSymbolAddress((void**)&dd,   g_dd);
    cudaGetSymbolAddress((void**)&h2,   g_h2);
    cudaGetSymbolAddress((void**)&opre, g_opre);

    const long EW = (long)BATCH*512*NPTS;

    // positional encoding -> [B,21,N]
    posenc_k<<<(BATCH*3*NPTS + 255)/256, 256>>>(x, h21);

    // conv1 (21->128) + relu
    mm_tf32_k<<<dim3(16,1,BATCH),256>>>(w1, h21, b1, h128, 128, NPTS, 21,
        21, 1, 0,   (long)NPTS, 1, (long)21*NPTS,   (long)128*NPTS, 1);
    // conv2 (128->256)
    mm_tf32_k<<<dim3(16,2,BATCH),256>>>(w2, h128, b2, h256, 256, NPTS, 128,
        128, 1, 0,  (long)NPTS, 1, (long)128*NPTS,  (long)256*NPTS, 0);
    // global max over N -> [B,256]
    rowmax_k<<<BATCH*256, 256>>>(h256, gm);
    // concat -> [B,512,N]
    concat_k<<<(int)((EW + 255)/256), 256>>>(h256, gm, hcat);
    // conv3 (512->512) + relu -> h
    mm_tf32_k<<<dim3(16,4,BATCH),256>>>(w3, hcat, b3, h, 512, NPTS, 512,
        512, 1, 0,  (long)NPTS, 1, (long)512*NPTS,  (long)512*NPTS, 1);
    // q/k projection (tied weights, computed once): [B,128,N]
    mm_tf32_k<<<dim3(16,1,BATCH),256>>>(wqk, h, nullptr, qk, 128, NPTS, 512,
        512, 1, 0,  (long)NPTS, 1, (long)512*NPTS,  (long)128*NPTS, 0);
    // v projection
    mm_tf32_k<<<dim3(16,4,BATCH),256>>>(wv, h, bv, xv, 512, NPTS, 512,
        512, 1, 0,  (long)NPTS, 1, (long)512*NPTS,  (long)512*NPTS, 0);
    // energy = qk^T * qk  -> attn [B,N,N]
    mm_tf32_k<<<dim3(16,16,BATCH),256>>>(qk, qk, nullptr, attn, NPTS, NPTS, 128,
        1, (long)NPTS, (long)128*NPTS,   (long)NPTS, 1, (long)128*NPTS,
        (long)NPTS*NPTS, 0);
    // softmax over k (rows)
    softmax_k<<<BATCH*NPTS, 256>>>(attn);
    // column sums over q
    colsum_k<<<dim3(NPTS/256, BATCH), 256>>>(attn, cs);
    // fold 1/(1e-9+colsum) into xv columns
    scalexv_k<<<(int)((EW + 255)/256), 256>>>(xv, cs);
    // x_r = xv_scaled @ attn^T : [B,512,N]
    mm_tf32_k<<<dim3(16,4,BATCH),256>>>(xv, attn, nullptr, xr, 512, NPTS, NPTS,
        (long)NPTS, 1, (long)512*NPTS,   1, (long)NPTS, (long)NPTS*NPTS,
        (long)512*NPTS, 0);
    // xr = h - xr
    sub_k<<<(int)((EW + 255)/256), 256>>>(h, xr);
    // trans conv: d = wt @ (h - xr) + bt
    mm_tf32_k<<<dim3(16,4,BATCH),256>>>(wt, xr, bt, dd, 512, NPTS, 512,
        512, 1, 0,  (long)NPTS, 1, (long)512*NPTS,  (long)512*NPTS, 0);
    // batch-norm (training-mode batch stats) + relu + residual
    bnstats_k<<<512, 256>>>(dd);
    bnapply_k<<<(int)((EW + 255)/256), 256>>>(h, dd, gamma, beta, h2);
    // conv4 (512->1024)
    mm_tf32_k<<<dim3(16,8,BATCH),256>>>(w4, h2, b4, opre, 1024, NPTS, 512,
        512, 1, 0,  (long)NPTS, 1, (long)512*NPTS,  (long)1024*NPTS, 0);
    // final max over N -> [B,1024]
    rowmax_k<<<BATCH*1024, 256>>>(opre, out);
}

// round 3
// speedup vs baseline: 3.6647x; 1.1424x over previous
#include <cuda_runtime.h>
#include <math.h>
#include <stdint.h>

#define BATCH 16
#define NPTS  2048
#define BM 128
#define BN 128
#define BKT 16
#define ASTRIDE 20      // padded k-stride for [row][k] tiles (bank-conflict-free)
#define BSTRIDE 136     // padded n-stride for [k][n] tiles (bank-conflict-free)
#define STAGE_FLOATS (BM*ASTRIDE + BM*ASTRIDE)   // As 2560 + Bs 2560
#define SMEM_BYTES (3 * STAGE_FLOATS * 4)        // 61440

// ---------------- scratch (device globals; no runtime allocation) ----------------
__device__ float g_h24 [(size_t)BATCH*24*NPTS];
__device__ float g_w1p [128*24];
__device__ float g_h128[(size_t)BATCH*128*NPTS];
__device__ float g_h256[(size_t)BATCH*256*NPTS];
__device__ float g_gm  [BATCH*256];
__device__ float g_hcat[(size_t)BATCH*512*NPTS];
__device__ float g_h   [(size_t)BATCH*512*NPTS];
__device__ float g_qk  [(size_t)BATCH*128*NPTS];
__device__ float g_qkT [(size_t)BATCH*NPTS*128];
__device__ float g_xv  [(size_t)BATCH*512*NPTS];
__device__ float g_attn[(size_t)BATCH*NPTS*NPTS];   // 256 MB
__device__ float g_cs  [BATCH*NPTS];
__device__ float g_xrT [(size_t)BATCH*NPTS*512];
__device__ float g_hmxr[(size_t)BATCH*512*NPTS];
__device__ float g_dd  [(size_t)BATCH*512*NPTS];
__device__ float g_mu  [512];
__device__ float g_rs  [512];
__device__ float g_h2  [(size_t)BATCH*512*NPTS];
__device__ float g_opre[(size_t)BATCH*1024*NPTS];   // 128 MB

// ---------------- helpers ----------------
__device__ __forceinline__ uint32_t f2tf(float f){
    uint32_t u;
    asm("cvt.rna.tf32.f32 %0, %1;" : "=r"(u) : "f"(f));
    return u;
}

__device__ __forceinline__ void mma_tf32(float c[4], uint32_t a0, uint32_t a1,
                                         uint32_t a2, uint32_t a3,
                                         uint32_t b0, uint32_t b1){
    asm volatile(
        "mma.sync.aligned.m16n8k8.row.col.f32.tf32.tf32.f32 "
        "{%0,%1,%2,%3}, {%4,%5,%6,%7}, {%8,%9}, {%0,%1,%2,%3};"
        : "+f"(c[0]), "+f"(c[1]), "+f"(c[2]), "+f"(c[3])
        : "r"(a0), "r"(a1), "r"(a2), "r"(a3), "r"(b0), "r"(b1));
}

__device__ __forceinline__ void cp16(uint32_t dst, const float* src, int sz){
    asm volatile("cp.async.cg.shared.global [%0], [%1], 16, %2;"
                 :: "r"(dst), "l"(src), "r"(sz));
}
__device__ __forceinline__ void cp_commit(){
    asm volatile("cp.async.commit_group;");
}
__device__ __forceinline__ void cp_wait1(){
    asm volatile("cp.async.wait_group 1;");
}

// ---------------- TF32 tensor-core GEMM, cp.async 3-stage pipeline ----------------
// C[b][m][n] = sum_k A[m][k] * B(k,n) (+bias[m]) (+relu)
// A: row-major [M,K] (k-contiguous), batch stride a_bat
// B: if !bT, [K,N] n-contiguous (B(k,n)=Bb[k*N+n]); if bT, [N,K] k-contiguous (B(k,n)=Bb[n*K+k])
__global__ __launch_bounds__(256, 2)
void mm_tc(const float* __restrict__ A, const float* __restrict__ B,
           const float* __restrict__ bias, float* __restrict__ C,
           int M, int N, int K,
           long a_bat, long b_bat, long c_bat, int relu, int bT)
{
    extern __shared__ float sm[];
    const float* Ab = A + (long)blockIdx.z * a_bat;
    const float* Bb = B + (long)blockIdx.z * b_bat;
    float*       Cb = C + (long)blockIdx.z * c_bat;
    const int bm = blockIdx.y * BM, bn = blockIdx.x * BN;
    const int tid = threadIdx.x;
    const int lane = tid & 31, wid = tid >> 5;
    const int wm = wid >> 2, wn = wid & 3;
    const int grp = lane >> 2, tig = lane & 3;
    const int ntiles = (K + BKT - 1) / BKT;

    const uint32_t sbase = (uint32_t)__cvta_generic_to_shared(sm);

    float acc[4][4][4];
#pragma unroll
    for (int i = 0; i < 4; i++)
#pragma unroll
        for (int j = 0; j < 4; j++)
#pragma unroll
            for (int r = 0; r < 4; r++) acc[i][j][r] = 0.f;

    auto prefetch = [&](int t){
        if (t >= ntiles) return;
        const int buf = t % 3;
        const uint32_t as0 = sbase + (uint32_t)(buf * STAGE_FLOATS) * 4u;
        const uint32_t bs0 = as0 + (uint32_t)(BM * ASTRIDE) * 4u;
        const int k0 = t * BKT;
        // A tile: 128 rows x 16 k, 16B chunks along k
#pragma unroll
        for (int i = 0; i < 2; i++) {
            int idx = tid + i*256;
            int mm = idx >> 2, kq = (idx & 3) << 2;
            long kg = (long)k0 + kq;
            long rem = ((long)K - kg) * 4;
            int sz = rem >= 16 ? 16 : (rem > 0 ? (int)rem : 0);
            const float* src = (sz > 0) ? (Ab + (long)(bm + mm)*K + kg) : Ab;
            cp16(as0 + (uint32_t)(mm*ASTRIDE + kq)*4u, src, sz);
        }
        if (!bT) {
            // B tile: 16 k-rows x 128 n, 16B chunks along n
#pragma unroll
            for (int i = 0; i < 2; i++) {
                int idx = tid + i*256;
                int kk = idx >> 5, nq = (idx & 31) << 2;
                long kg = (long)k0 + kk;
                int sz = (kg < K) ? 16 : 0;
                const float* src = (sz > 0) ? (Bb + kg*(long)N + (bn + nq)) : Bb;
                cp16(bs0 + (uint32_t)(kk*BSTRIDE + nq)*4u, src, sz);
            }
        } else {
            // B tile: 128 n-rows x 16 k, 16B chunks along k
#pragma unroll
            for (int i = 0; i < 2; i++) {
                int idx = tid + i*256;
                int nn = idx >> 2, kq = (idx & 3) << 2;
                long kg = (long)k0 + kq;
                long rem = ((long)K - kg) * 4;
                int sz = rem >= 16 ? 16 : (rem > 0 ? (int)rem : 0);
                const float* src = (sz > 0) ? (Bb + (long)(bn + nn)*K + kg) : Bb;
                cp16(bs0 + (uint32_t)(nn*ASTRIDE + kq)*4u, src, sz);
            }
        }
    };

    prefetch(0); cp_commit();
    prefetch(1); cp_commit();

    for (int t = 0; t < ntiles; t++) {
        cp_wait1();
        __syncthreads();
        const float* As = sm + (t % 3) * STAGE_FLOATS;
        const float* Bs = As + BM * ASTRIDE;

#pragma unroll
        for (int ks = 0; ks < 2; ks++) {
            const int kb = ks * 8;
            uint32_t af[4][4], bf[4][2];
#pragma unroll
            for (int i = 0; i < 4; i++) {
                int m0 = wm*64 + i*16 + grp;
                const float* r0 = As + m0*ASTRIDE;
                const float* r1 = As + (m0+8)*ASTRIDE;
                af[i][0] = f2tf(r0[kb+tig]);
                af[i][1] = f2tf(r1[kb+tig]);
                af[i][2] = f2tf(r0[kb+tig+4]);
                af[i][3] = f2tf(r1[kb+tig+4]);
            }
            if (!bT) {
#pragma unroll
                for (int j = 0; j < 4; j++) {
                    int n0 = wn*32 + j*8 + grp;
                    bf[j][0] = f2tf(Bs[(kb+tig)*BSTRIDE + n0]);
                    bf[j][1] = f2tf(Bs[(kb+tig+4)*BSTRIDE + n0]);
                }
            } else {
#pragma unroll
                for (int j = 0; j < 4; j++) {
                    int n0 = wn*32 + j*8 + grp;
                    bf[j][0] = f2tf(Bs[n0*ASTRIDE + kb+tig]);
                    bf[j][1] = f2tf(Bs[n0*ASTRIDE + kb+tig+4]);
                }
            }
#pragma unroll
            for (int i = 0; i < 4; i++)
#pragma unroll
                for (int j = 0; j < 4; j++)
                    mma_tf32(acc[i][j], af[i][0], af[i][1], af[i][2], af[i][3],
                             bf[j][0], bf[j][1]);
        }
        prefetch(t + 2); cp_commit();
    }

#pragma unroll
    for (int i = 0; i < 4; i++) {
        int mg = bm + wm*64 + i*16 + grp;
        float bi0 = bias ? bias[mg]   : 0.f;
        float bi1 = bias ? bias[mg+8] : 0.f;
#pragma unroll
        for (int j = 0; j < 4; j++) {
            int ng = bn + wn*32 + j*8 + tig*2;
            float2 v0, v1;
            v0.x = acc[i][j][0] + bi0; v0.y = acc[i][j][1] + bi0;
            v1.x = acc[i][j][2] + bi1; v1.y = acc[i][j][3] + bi1;
            if (relu) {
                v0.x = fmaxf(v0.x, 0.f); v0.y = fmaxf(v0.y, 0.f);
                v1.x = fmaxf(v1.x, 0.f); v1.y = fmaxf(v1.y, 0.f);
            }
            *(float2*)&Cb[(long)mg*N + ng]     = v0;
            *(float2*)&Cb[(long)(mg+8)*N + ng] = v1;
        }
    }
}

// ---------------- positional encoding (24 channels, 3 zero-padded) ----------------
__global__ void posenc_k(const float* __restrict__ x, float* __restrict__ h24)
{
    int idx = blockIdx.x*blockDim.x + threadIdx.x;
    if (idx >= BATCH*3*NPTS) return;
    int n = idx % NPTS; int r = idx / NPTS;
    int dim = r % 3, b = r / 3;
    float t = x[((long)b*3 + dim)*NPTS + n];
    float* o = h24 + (long)b*24*NPTS + n;
    o[(long)(dim     )*NPTS] = t;
    o[(long)(3  + dim)*NPTS] = sinf(t);
    o[(long)(6  + dim)*NPTS] = cosf(t);
    o[(long)(9  + dim)*NPTS] = sinf(2.f*t);
    o[(long)(12 + dim)*NPTS] = cosf(2.f*t);
    o[(long)(15 + dim)*NPTS] = sinf(4.f*t);
    o[(long)(18 + dim)*NPTS] = cosf(4.f*t);
    o[(long)(21 + dim)*NPTS] = 0.f;
}

// ---------------- pad w1 [128,21] -> [128,24] ----------------
__global__ void w1pad_k(const float* __restrict__ w1, float* __restrict__ w1p)
{
    int i = blockIdx.x*256 + threadIdx.x;
    if (i >= 128*24) return;
    int m = i / 24, k = i % 24;
    w1p[i] = (k < 21) ? w1[m*21 + k] : 0.f;
}

// ---------------- row max over NPTS contiguous elements ----------------
__global__ void rowmax_k(const float* __restrict__ in, float* __restrict__ out)
{
    int r = blockIdx.x;
    const float* p = in + (long)r*NPTS;
    float m = -3.402823466e38f;
    for (int i = threadIdx.x; i < NPTS; i += 256) m = fmaxf(m, p[i]);
    __shared__ float sh[8];
#pragma unroll
    for (int o = 16; o > 0; o >>= 1) m = fmaxf(m, __shfl_xor_sync(0xffffffffu, m, o));
    if ((threadIdx.x & 31) == 0) sh[threadIdx.x >> 5] = m;
    __syncthreads();
    if (threadIdx.x == 0) {
        float v = sh[0];
#pragma unroll
        for (int i = 1; i < 8; i++) v = fmaxf(v, sh[i]);
        out[r] = v;
    }
}

// ---------------- concat [h256 ; broadcast gmax] -> [B,512,N] ----------------
__global__ void concat_k(const float* __restrict__ h256, const float* __restrict__ gm,
                         float* __restrict__ hcat)
{
    long idx = (long)blockIdx.x*blockDim.x + threadIdx.x;
    if (idx >= (long)BATCH*512*NPTS) return;
    int n = idx % NPTS;
    int c = (idx / NPTS) % 512;
    int b = idx / ((long)512*NPTS);
    hcat[idx] = (c < 256) ? h256[((long)b*256 + c)*NPTS + n] : gm[b*256 + (c - 256)];
}

// ---------------- transpose qk [128,N] -> qkT [N,128] per batch ----------------
__global__ void tqk_k(const float* __restrict__ qk, float* __restrict__ qkT)
{
    __shared__ float s[32][33];
    int b = blockIdx.z;
    int n0 = blockIdx.x*32, c0 = blockIdx.y*32;
    const float* src = qk + (long)b*128*NPTS;
    float*       dst = qkT + (long)b*NPTS*128;
    int x = threadIdx.x, y = threadIdx.y;  // block (32,8)
#pragma unroll
    for (int i = 0; i < 4; i++)
        s[y+8*i][x] = src[(long)(c0+y+8*i)*NPTS + n0+x];
    __syncthreads();
#pragma unroll
    for (int i = 0; i < 4; i++)
        dst[(long)(n0+y+8*i)*128 + c0+x] = s[x][y+8*i];
}

// ---------------- softmax over last dim (rows of attn), in place ----------------
__global__ void softmax_k(float* __restrict__ attn)
{
    size_t row = blockIdx.x;
    float* p = attn + row * (size_t)NPTS;
    int t = threadIdx.x;
    float v[8];
    float m = -3.402823466e38f;
#pragma unroll
    for (int i = 0; i < 8; i++) { v[i] = p[t + 256*i]; m = fmaxf(m, v[i]); }
    __shared__ float sh[8];
#pragma unroll
    for (int o = 16; o > 0; o >>= 1) m = fmaxf(m, __shfl_xor_sync(0xffffffffu, m, o));
    if ((t & 31) == 0) sh[t >> 5] = m;
    __syncthreads();
    float rm = sh[0];
#pragma unroll
    for (int i = 1; i < 8; i++) rm = fmaxf(rm, sh[i]);
    __syncthreads();
    float s = 0.f;
#pragma unroll
    for (int i = 0; i < 8; i++) { v[i] = expf(v[i] - rm); s += v[i]; }
#pragma unroll
    for (int o = 16; o > 0; o >>= 1) s += __shfl_xor_sync(0xffffffffu, s, o);
    if ((t & 31) == 0) sh[t >> 5] = s;
    __syncthreads();
    float rs = 0.f;
#pragma unroll
    for (int i = 0; i < 8; i++) rs += sh[i];
    float inv = 1.f / rs;
#pragma unroll
    for (int i = 0; i < 8; i++) p[t + 256*i] = v[i] * inv;
}

// ---------------- column sums over q (per b,k) ----------------
__global__ void colsum_k(const float* __restrict__ attn, float* __restrict__ cs)
{
    int k = blockIdx.x*256 + threadIdx.x;
    int b = blockIdx.y;
    const float* p = attn + (size_t)b*NPTS*NPTS + k;
    float s = 0.f;
#pragma unroll 8
    for (int q = 0; q < NPTS; q++) s += p[(size_t)q*NPTS];
    cs[b*NPTS + k] = s;
}

// ---------------- fold double-normalization into xv columns ----------------
__global__ void scalexv_k(float* __restrict__ xv, const float* __restrict__ cs)
{
    long idx = (long)blockIdx.x*blockDim.x + threadIdx.x;
    if (idx >= (long)BATCH*512*NPTS) return;
    int k = idx % NPTS;
    int b = idx / ((long)512*NPTS);
    xv[idx] *= 1.f / (1e-9f + cs[b*NPTS + k]);
}

// ---------------- hmxr[c][n] = h[c][n] - xrT[n][c] (tiled transpose-sub) ----------------
__global__ void tsub_k(const float* __restrict__ h, const float* __restrict__ xrT,
                       float* __restrict__ o)
{
    __shared__ float s[32][33];
    int b = blockIdx.z;
    int n0 = blockIdx.x*32, c0 = blockIdx.y*32;
    const float* xb = xrT + (long)b*NPTS*512;
    const float* hb = h + (long)b*512*NPTS;
    float*       ob = o + (long)b*512*NPTS;
    int x = threadIdx.x, y = threadIdx.y;  // block (32,8)
#pragma unroll
    for (int i = 0; i < 4; i++)
        s[y+8*i][x] = xb[(long)(n0+y+8*i)*512 + c0+x];     // s[n_local][c_local]
    __syncthreads();
#pragma unroll
    for (int i = 0; i < 4; i++) {
        int c = c0 + y + 8*i;
        long off = (long)c*NPTS + n0 + x;
        ob[off] = hb[off] - s[x][y+8*i];
    }
}

// ---------------- BN batch stats per channel ----------------
__global__ void bnstats_k(const float* __restrict__ d)
{
    int c = blockIdx.x;
    int t = threadIdx.x;
    double s = 0.0, s2 = 0.0;
    for (int i = t; i < BATCH*NPTS; i += 256) {
        int b = i / NPTS, n = i % NPTS;
        float v = d[((long)b*512 + c)*NPTS + n];
        s += v; s2 += (double)v*v;
    }
    __shared__ double sh[256], sh2[256];
    sh[t] = s; sh2[t] = s2; __syncthreads();
    for (int o = 128; o > 0; o >>= 1) {
        if (t < o) { sh[t] += sh[t+o]; sh2[t] += sh2[t+o]; }
        __syncthreads();
    }
    if (t == 0) {
        double mu  = sh[0]  / (double)(BATCH*NPTS);
        double var = sh2[0] / (double)(BATCH*NPTS) - mu*mu;
        g_mu[c] = (float)mu;
        g_rs[c] = (float)(1.0 / sqrt(var + 1e-5));
    }
}

// ---------------- h2 = h + relu(gamma*(d-mu)*rsig + beta) ----------------
__global__ void bnapply_k(const float* __restrict__ h, const float* __restrict__ d,
                          const float* __restrict__ gamma, const float* __restrict__ beta,
                          float* __restrict__ h2)
{
    long idx = (long)blockIdx.x*blockDim.x + threadIdx.x;
    if (idx >= (long)BATCH*512*NPTS) return;
    int c = (idx / NPTS) % 512;
    float v = gamma[c] * (d[idx] - g_mu[c]) * g_rs[c] + beta[c];
    h2[idx] = h[idx] + fmaxf(v, 0.f);
}

// ---------------- launch ----------------
extern "C" void kernel_launch(void* const* d_in, const int* in_sizes, int n_in,
                              void* d_out, int out_size)
{
    const float* x    = (const float*)d_in[0];
    const float* w1   = (const float*)d_in[1];
    const float* b1   = (const float*)d_in[2];
    const float* w2   = (const float*)d_in[3];
    const float* b2   = (const float*)d_in[4];
    const float* w3   = (const float*)d_in[5];
    const float* b3   = (const float*)d_in[6];
    const float* w4   = (const float*)d_in[7];
    const float* b4   = (const float*)d_in[8];
    const float* wqk  = (const float*)d_in[9];
    const float* wv   = (const float*)d_in[10];
    const float* bv   = (const float*)d_in[11];
    const float* wt   = (const float*)d_in[12];
    const float* bt   = (const float*)d_in[13];
    const float* gamma= (const float*)d_in[14];
    const float* beta = (const float*)d_in[15];
    float* out = (float*)d_out;

    static bool attr_set = false;
    if (!attr_set) {
        cudaFuncSetAttribute(mm_tc, cudaFuncAttributeMaxDynamicSharedMemorySize, SMEM_BYTES);
        attr_set = true;
    }

    float *h24,*w1p,*h128,*h256,*gm,*hcat,*h,*qk,*qkT,*xv,*attn,*cs,*xrT,*hmxr,*dd,*h2,*opre;
    cudaGetSymbolAddress((void**)&h24,  g_h24);
    cudaGetSymbolAddress((void**)&w1p,  g_w1p);
    cudaGetSymbolAddress((void**)&h128, g_h128);
    cudaGetSymbolAddress((void**)&h256, g_h256);
    cudaGetSymbolAddress((void**)&gm,   g_gm);
    cudaGetSymbolAddress((void**)&hcat, g_hcat);
    cudaGetSymbolAddress((void**)&h,    g_h);
    cudaGetSymbolAddress((void**)&qk,   g_qk);
    cudaGetSymbolAddress((void**)&qkT,  g_qkT);
    cudaGetSymbolAddress((void**)&xv,   g_xv);
    cudaGetSymbolAddress((void**)&attn, g_attn);
    cudaGetSymbolAddress((void**)&cs,   g_cs);
    cudaGetSymbolAddress((void**)&xrT,  g_xrT);
    cudaGetSymbolAddress((void**)&hmxr, g_hmxr);
    cudaGetSymbolAddress((void**)&dd,   g_dd);
    cudaGetSymbolAddress((void**)&h2,   g_h2);
    cudaGetSymbolAddress((void**)&opre, g_opre);

    const long EW = (long)BATCH*512*NPTS;

    posenc_k<<<(BATCH*3*NPTS + 255)/256, 256>>>(x, h24);
    w1pad_k<<<(128*24 + 255)/256, 256>>>(w1, w1p);

    // conv1 (24->128, zero-padded) + relu
    mm_tc<<<dim3(16,1,BATCH),256,SMEM_BYTES>>>(w1p, h24, b1, h128, 128, NPTS, 24,
        0, (long)24*NPTS, (long)128*NPTS, 1, 0);
    // conv2 (128->256)
    mm_tc<<<dim3(16,2,BATCH),256,SMEM_BYTES>>>(w2, h128, b2, h256, 256, NPTS, 128,
        0, (long)128*NPTS, (long)256*NPTS, 0, 0);
    rowmax_k<<<BATCH*256, 256>>>(h256, gm);
    concat_k<<<(int)((EW + 255)/256), 256>>>(h256, gm, hcat);
    // conv3 (512->512) + relu -> h
    mm_tc<<<dim3(16,4,BATCH),256,SMEM_BYTES>>>(w3, hcat, b3, h, 512, NPTS, 512,
        0, (long)512*NPTS, (long)512*NPTS, 1, 0);
    // q/k projection (tied weights)
    mm_tc<<<dim3(16,1,BATCH),256,SMEM_BYTES>>>(wqk, h, nullptr, qk, 128, NPTS, 512,
        0, (long)512*NPTS, (long)128*NPTS, 0, 0);
    tqk_k<<<dim3(NPTS/32, 4, BATCH), dim3(32,8)>>>(qk, qkT);
    // v projection
    mm_tc<<<dim3(16,4,BATCH),256,SMEM_BYTES>>>(wv, h, bv, xv, 512, NPTS, 512,
        0, (long)512*NPTS, (long)512*NPTS, 0, 0);
    // energy = qkT @ qk  -> attn [B,N,N]
    mm_tc<<<dim3(16,16,BATCH),256,SMEM_BYTES>>>(qkT, qk, nullptr, attn, NPTS, NPTS, 128,
        (long)NPTS*128, (long)128*NPTS, (long)NPTS*NPTS, 0, 0);
    softmax_k<<<BATCH*NPTS, 256>>>(attn);
    colsum_k<<<dim3(NPTS/256, BATCH), 256>>>(attn, cs);
    scalexv_k<<<(int)((EW + 255)/256), 256>>>(xv, cs);
    // x_r^T[q][c] = sum_k attn[q,k]*xv[c,k]  (B in k-contiguous mode)
    mm_tc<<<dim3(4,16,BATCH),256,SMEM_BYTES>>>(attn, xv, nullptr, xrT, NPTS, 512, NPTS,
        (long)NPTS*NPTS, (long)512*NPTS, (long)NPTS*512, 0, 1);
    // hmxr = h - x_r (with transpose)
    tsub_k<<<dim3(NPTS/32, 16, BATCH), dim3(32,8)>>>(h, xrT, hmxr);
    // trans conv: d = wt @ (h - x_r) + bt
    mm_tc<<<dim3(16,4,BATCH),256,SMEM_BYTES>>>(wt, hmxr, bt, dd, 512, NPTS, 512,
        0, (long)512*NPTS, (long)512*NPTS, 0, 0);
    bnstats_k<<<512, 256>>>(dd);
    bnapply_k<<<(int)((EW + 255)/256), 256>>>(h, dd, gamma, beta, h2);
    // conv4 (512->1024)
    mm_tc<<<dim3(16,8,BATCH),256,SMEM_BYTES>>>(w4, h2, b4, opre, 1024, NPTS, 512,
        0, (long)512*NPTS, (long)1024*NPTS, 0, 0);
    rowmax_k<<<BATCH*1024, 256>>>(opre, out);
}

// round 4
// speedup vs baseline: 4.2298x; 1.1542x over previous
#include <cuda_runtime.h>
#include <math.h>
#include <stdint.h>

#define BATCH 16
#define NPTS  2048
#define BM 128
#define BN 128
#define BKT 16
#define ASTRIDE 20      // padded k-stride for [row][k] tiles
#define BSTRIDE 136     // padded n-stride for [k][n] tiles
#define STAGE_FLOATS (BM*ASTRIDE + BM*ASTRIDE)
#define SMEM_BYTES (3 * STAGE_FLOATS * 4)        // 61440

// ---------------- scratch (device globals) ----------------
__device__ float g_h24 [(size_t)BATCH*24*NPTS];
__device__ float g_w1p [128*24];
__device__ float g_w2r [256*128];
__device__ float g_w3r [512*512];
__device__ float g_w4r [1024*512];
__device__ float g_wqkr[128*512];
__device__ float g_wvr [512*512];
__device__ float g_wtr [512*512];
__device__ float g_h128[(size_t)BATCH*128*NPTS];
__device__ float g_gm  [BATCH*256];
__device__ float g_hcat[(size_t)BATCH*512*NPTS];
__device__ float g_h   [(size_t)BATCH*512*NPTS];
__device__ float g_qk  [(size_t)BATCH*128*NPTS];
__device__ float g_qkT [(size_t)BATCH*NPTS*128];
__device__ float g_xv  [(size_t)BATCH*512*NPTS];
__device__ float g_attn[(size_t)BATCH*NPTS*NPTS];   // 256 MB
__device__ float g_cs  [BATCH*NPTS];
__device__ float g_xrT [(size_t)BATCH*NPTS*512];
__device__ float g_hmxr[(size_t)BATCH*512*NPTS];
__device__ float g_dd  [(size_t)BATCH*512*NPTS];
__device__ float g_mu  [512];
__device__ float g_rs  [512];
__device__ float g_h2  [(size_t)BATCH*512*NPTS];
__device__ float g_opre[(size_t)BATCH*1024*NPTS];   // 128 MB

// ---------------- helpers ----------------
__device__ __forceinline__ uint32_t f2tf(float f){
    uint32_t u;
    asm("cvt.rna.tf32.f32 %0, %1;" : "=r"(u) : "f"(f));
    return u;
}
__device__ __forceinline__ float rnd(float f){ return __uint_as_float(f2tf(f)); }

__device__ __forceinline__ void mma_tf32(float c[4], uint32_t a0, uint32_t a1,
                                         uint32_t a2, uint32_t a3,
                                         uint32_t b0, uint32_t b1){
    asm volatile(
        "mma.sync.aligned.m16n8k8.row.col.f32.tf32.tf32.f32 "
        "{%0,%1,%2,%3}, {%4,%5,%6,%7}, {%8,%9}, {%0,%1,%2,%3};"
        : "+f"(c[0]), "+f"(c[1]), "+f"(c[2]), "+f"(c[3])
        : "r"(a0), "r"(a1), "r"(a2), "r"(a3), "r"(b0), "r"(b1));
}

__device__ __forceinline__ void cp16(uint32_t dst, const float* src, int sz){
    asm volatile("cp.async.cg.shared.global [%0], [%1], 16, %2;"
                 :: "r"(dst), "l"(src), "r"(sz));
}
__device__ __forceinline__ void cp_commit(){ asm volatile("cp.async.commit_group;"); }
__device__ __forceinline__ void cp_wait1(){ asm volatile("cp.async.wait_group 1;"); }

// ---------------- TF32 tensor-core GEMM (operands pre-rounded unless CVTB) ----------------
// C[b][m][n] = sum_k A[m][k]*B(k,n) (+bias[m]) (+relu) (RNDC: round output to tf32)
// A: row-major [M,K] k-contiguous. B: !bT -> [K,N] n-contig ; bT -> [N,K] k-contig
template<int CVTB, int RNDC>
__global__ __launch_bounds__(256, 2)
void mm_tc(const float* __restrict__ A, const float* __restrict__ B,
           const float* __restrict__ bias, float* __restrict__ C,
           int M, int N, int K,
           long a_bat, long b_bat, long c_bat, int relu, int bT)
{
    extern __shared__ float sm[];
    const float* Ab = A + (long)blockIdx.z * a_bat;
    const float* Bb = B + (long)blockIdx.z * b_bat;
    float*       Cb = C + (long)blockIdx.z * c_bat;
    const int bm = blockIdx.y * BM, bn = blockIdx.x * BN;
    const int tid = threadIdx.x;
    const int lane = tid & 31, wid = tid >> 5;
    const int wm = wid >> 2, wn = wid & 3;
    const int grp = lane >> 2, tig = lane & 3;
    const int ntiles = (K + BKT - 1) / BKT;

    const uint32_t sbase = (uint32_t)__cvta_generic_to_shared(sm);

    float acc[4][4][4];
#pragma unroll
    for (int i = 0; i < 4; i++)
#pragma unroll
        for (int j = 0; j < 4; j++)
#pragma unroll
            for (int r = 0; r < 4; r++) acc[i][j][r] = 0.f;

    auto prefetch = [&](int t){
        if (t >= ntiles) return;
        const int buf = t % 3;
        const uint32_t as0 = sbase + (uint32_t)(buf * STAGE_FLOATS) * 4u;
        const uint32_t bs0 = as0 + (uint32_t)(BM * ASTRIDE) * 4u;
        const int k0 = t * BKT;
#pragma unroll
        for (int i = 0; i < 2; i++) {
            int idx = tid + i*256;
            int mm = idx >> 2, kq = (idx & 3) << 2;
            long kg = (long)k0 + kq;
            long rem = ((long)K - kg) * 4;
            int sz = rem >= 16 ? 16 : (rem > 0 ? (int)rem : 0);
            const float* src = (sz > 0) ? (Ab + (long)(bm + mm)*K + kg) : Ab;
            cp16(as0 + (uint32_t)(mm*ASTRIDE + kq)*4u, src, sz);
        }
        if (!bT) {
#pragma unroll
            for (int i = 0; i < 2; i++) {
                int idx = tid + i*256;
                int kk = idx >> 5, nq = (idx & 31) << 2;
                long kg = (long)k0 + kk;
                int sz = (kg < K) ? 16 : 0;
                const float* src = (sz > 0) ? (Bb + kg*(long)N + (bn + nq)) : Bb;
                cp16(bs0 + (uint32_t)(kk*BSTRIDE + nq)*4u, src, sz);
            }
        } else {
#pragma unroll
            for (int i = 0; i < 2; i++) {
                int idx = tid + i*256;
                int nn = idx >> 2, kq = (idx & 3) << 2;
                long kg = (long)k0 + kq;
                long rem = ((long)K - kg) * 4;
                int sz = rem >= 16 ? 16 : (rem > 0 ? (int)rem : 0);
                const float* src = (sz > 0) ? (Bb + (long)(bn + nn)*K + kg) : Bb;
                cp16(bs0 + (uint32_t)(nn*ASTRIDE + kq)*4u, src, sz);
            }
        }
    };

    prefetch(0); cp_commit();
    prefetch(1); cp_commit();

    for (int t = 0; t < ntiles; t++) {
        cp_wait1();
        __syncthreads();
        const float* As = sm + (t % 3) * STAGE_FLOATS;
        const float* Bs = As + BM * ASTRIDE;
        const uint32_t* Asu = (const uint32_t*)As;
        const uint32_t* Bsu = (const uint32_t*)Bs;

#pragma unroll
        for (int ks = 0; ks < 2; ks++) {
            const int kb = ks * 8;
            uint32_t af[4][4], bf[4][2];
#pragma unroll
            for (int i = 0; i < 4; i++) {
                int m0 = wm*64 + i*16 + grp;
                const uint32_t* r0 = Asu + m0*ASTRIDE;
                const uint32_t* r1 = r0 + 8*ASTRIDE;
                af[i][0] = r0[kb+tig];
                af[i][1] = r1[kb+tig];
                af[i][2] = r0[kb+tig+4];
                af[i][3] = r1[kb+tig+4];
            }
            if (!bT) {
#pragma unroll
                for (int j = 0; j < 4; j++) {
                    int n0 = wn*32 + j*8 + grp;
                    uint32_t v0 = Bsu[(kb+tig)*BSTRIDE + n0];
                    uint32_t v1 = Bsu[(kb+tig+4)*BSTRIDE + n0];
                    bf[j][0] = CVTB ? f2tf(__uint_as_float(v0)) : v0;
                    bf[j][1] = CVTB ? f2tf(__uint_as_float(v1)) : v1;
                }
            } else {
#pragma unroll
                for (int j = 0; j < 4; j++) {
                    int n0 = wn*32 + j*8 + grp;
                    uint32_t v0 = Bsu[n0*ASTRIDE + kb+tig];
                    uint32_t v1 = Bsu[n0*ASTRIDE + kb+tig+4];
                    bf[j][0] = CVTB ? f2tf(__uint_as_float(v0)) : v0;
                    bf[j][1] = CVTB ? f2tf(__uint_as_float(v1)) : v1;
                }
            }
#pragma unroll
            for (int i = 0; i < 4; i++)
#pragma unroll
                for (int j = 0; j < 4; j++)
                    mma_tf32(acc[i][j], af[i][0], af[i][1], af[i][2], af[i][3],
                             bf[j][0], bf[j][1]);
        }
        prefetch(t + 2); cp_commit();
    }

#pragma unroll
    for (int i = 0; i < 4; i++) {
        int mg = bm + wm*64 + i*16 + grp;
        float bi0 = bias ? bias[mg]   : 0.f;
        float bi1 = bias ? bias[mg+8] : 0.f;
#pragma unroll
        for (int j = 0; j < 4; j++) {
            int ng = bn + wn*32 + j*8 + tig*2;
            float2 v0, v1;
            v0.x = acc[i][j][0] + bi0; v0.y = acc[i][j][1] + bi0;
            v1.x = acc[i][j][2] + bi1; v1.y = acc[i][j][3] + bi1;
            if (relu) {
                v0.x = fmaxf(v0.x, 0.f); v0.y = fmaxf(v0.y, 0.f);
                v1.x = fmaxf(v1.x, 0.f); v1.y = fmaxf(v1.y, 0.f);
            }
            if (RNDC) {
                v0.x = rnd(v0.x); v0.y = rnd(v0.y);
                v1.x = rnd(v1.x); v1.y = rnd(v1.y);
            }
            *(float2*)&Cb[(long)mg*N + ng]     = v0;
            *(float2*)&Cb[(long)(mg+8)*N + ng] = v1;
        }
    }
}

// ---------------- tf32-round copy (weights) ----------------
__global__ void rndcopy_k(const float4* __restrict__ src, float4* __restrict__ dst, int n4)
{
    int i = blockIdx.x*256 + threadIdx.x;
    if (i >= n4) return;
    float4 v = src[i];
    v.x = rnd(v.x); v.y = rnd(v.y); v.z = rnd(v.z); v.w = rnd(v.w);
    dst[i] = v;
}

// ---------------- positional encoding (24 ch, rounded) ----------------
__global__ void posenc_k(const float* __restrict__ x, float* __restrict__ h24)
{
    int idx = blockIdx.x*blockDim.x + threadIdx.x;
    if (idx >= BATCH*3*NPTS) return;
    int n = idx % NPTS; int r = idx / NPTS;
    int dim = r % 3, b = r / 3;
    float t = x[((long)b*3 + dim)*NPTS + n];
    float* o = h24 + (long)b*24*NPTS + n;
    o[(long)(dim     )*NPTS] = rnd(t);
    o[(long)(3  + dim)*NPTS] = rnd(sinf(t));
    o[(long)(6  + dim)*NPTS] = rnd(cosf(t));
    o[(long)(9  + dim)*NPTS] = rnd(sinf(2.f*t));
    o[(long)(12 + dim)*NPTS] = rnd(cosf(2.f*t));
    o[(long)(15 + dim)*NPTS] = rnd(sinf(4.f*t));
    o[(long)(18 + dim)*NPTS] = rnd(cosf(4.f*t));
    o[(long)(21 + dim)*NPTS] = 0.f;
}

// ---------------- pad+round w1 [128,21] -> [128,24] ----------------
__global__ void w1pad_k(const float* __restrict__ w1, float* __restrict__ w1p)
{
    int i = blockIdx.x*256 + threadIdx.x;
    if (i >= 128*24) return;
    int m = i / 24, k = i % 24;
    w1p[i] = (k < 21) ? rnd(w1[m*21 + k]) : 0.f;
}

// ---------------- row max over NPTS contiguous elements (float4) ----------------
__global__ void rowmax_k(const float* __restrict__ in, float* __restrict__ out)
{
    int r = blockIdx.x;
    const float4* p = (const float4*)(in + (long)r*NPTS);
    float m = -3.402823466e38f;
#pragma unroll
    for (int i = 0; i < 2; i++) {
        float4 v = p[threadIdx.x + 256*i];
        m = fmaxf(m, fmaxf(fmaxf(v.x, v.y), fmaxf(v.z, v.w)));
    }
    __shared__ float sh[8];
#pragma unroll
    for (int o = 16; o > 0; o >>= 1) m = fmaxf(m, __shfl_xor_sync(0xffffffffu, m, o));
    if ((threadIdx.x & 31) == 0) sh[threadIdx.x >> 5] = m;
    __syncthreads();
    if (threadIdx.x == 0) {
        float v = sh[0];
#pragma unroll
        for (int i = 1; i < 8; i++) v = fmaxf(v, sh[i]);
        out[r] = v;
    }
}

// ---------------- row max over first 256 channels of hcat ----------------
__global__ void rowmax256_k(const float* __restrict__ hcat, float* __restrict__ gm)
{
    int r = blockIdx.x;                 // b*256 + c
    int b = r >> 8, c = r & 255;
    const float4* p = (const float4*)(hcat + ((long)b*512 + c)*NPTS);
    float m = -3.402823466e38f;
#pragma unroll
    for (int i = 0; i < 2; i++) {
        float4 v = p[threadIdx.x + 256*i];
        m = fmaxf(m, fmaxf(fmaxf(v.x, v.y), fmaxf(v.z, v.w)));
    }
    __shared__ float sh[8];
#pragma unroll
    for (int o = 16; o > 0; o >>= 1) m = fmaxf(m, __shfl_xor_sync(0xffffffffu, m, o));
    if ((threadIdx.x & 31) == 0) sh[threadIdx.x >> 5] = m;
    __syncthreads();
    if (threadIdx.x == 0) {
        float v = sh[0];
#pragma unroll
        for (int i = 1; i < 8; i++) v = fmaxf(v, sh[i]);
        gm[r] = v;
    }
}

// ---------------- broadcast gm into hcat channels 256..511 ----------------
__global__ void bcast_k(const float* __restrict__ gm, float* __restrict__ hcat)
{
    long idx = (long)blockIdx.x*256 + threadIdx.x;     // over BATCH*256*NPTS
    if (idx >= (long)BATCH*256*NPTS) return;
    int n = idx % NPTS;
    int c = (idx / NPTS) % 256;
    int b = idx / ((long)256*NPTS);
    hcat[((long)b*512 + 256 + c)*NPTS + n] = gm[b*256 + c];
}

// ---------------- transpose qk [128,N] -> qkT [N,128] ----------------
__global__ void tqk_k(const float* __restrict__ qk, float* __restrict__ qkT)
{
    __shared__ float s[32][33];
    int b = blockIdx.z;
    int n0 = blockIdx.x*32, c0 = blockIdx.y*32;
    const float* src = qk + (long)b*128*NPTS;
    float*       dst = qkT + (long)b*NPTS*128;
    int x = threadIdx.x, y = threadIdx.y;
#pragma unroll
    for (int i = 0; i < 4; i++)
        s[y+8*i][x] = src[(long)(c0+y+8*i)*NPTS + n0+x];
    __syncthreads();
#pragma unroll
    for (int i = 0; i < 4; i++)
        dst[(long)(n0+y+8*i)*128 + c0+x] = s[x][y+8*i];
}

// ---------------- softmax rows, in place, float4, rounded output ----------------
__global__ void softmax_k(float* __restrict__ attn)
{
    size_t row = blockIdx.x;
    float4* p = (float4*)(attn + row * (size_t)NPTS);
    int t = threadIdx.x;
    float4 v[2];
    float m = -3.402823466e38f;
#pragma unroll
    for (int i = 0; i < 2; i++) {
        v[i] = p[t + 256*i];
        m = fmaxf(m, fmaxf(fmaxf(v[i].x, v[i].y), fmaxf(v[i].z, v[i].w)));
    }
    __shared__ float sh[8];
#pragma unroll
    for (int o = 16; o > 0; o >>= 1) m = fmaxf(m, __shfl_xor_sync(0xffffffffu, m, o));
    if ((t & 31) == 0) sh[t >> 5] = m;
    __syncthreads();
    float rm = sh[0];
#pragma unroll
    for (int i = 1; i < 8; i++) rm = fmaxf(rm, sh[i]);
    __syncthreads();
    float s = 0.f;
#pragma unroll
    for (int i = 0; i < 2; i++) {
        v[i].x = expf(v[i].x - rm); v[i].y = expf(v[i].y - rm);
        v[i].z = expf(v[i].z - rm); v[i].w = expf(v[i].w - rm);
        s += v[i].x + v[i].y + v[i].z + v[i].w;
    }
#pragma unroll
    for (int o = 16; o > 0; o >>= 1) s += __shfl_xor_sync(0xffffffffu, s, o);
    if ((t & 31) == 0) sh[t >> 5] = s;
    __syncthreads();
    float rs = 0.f;
#pragma unroll
    for (int i = 0; i < 8; i++) rs += sh[i];
    float inv = 1.f / rs;
#pragma unroll
    for (int i = 0; i < 2; i++) {
        v[i].x = rnd(v[i].x * inv); v[i].y = rnd(v[i].y * inv);
        v[i].z = rnd(v[i].z * inv); v[i].w = rnd(v[i].w * inv);
        p[t + 256*i] = v[i];
    }
}

// ---------------- column sums over q ----------------
__global__ void colsum_k(const float* __restrict__ attn, float* __restrict__ cs)
{
    int k = blockIdx.x*256 + threadIdx.x;
    int b = blockIdx.y;
    const float* p = attn + (size_t)b*NPTS*NPTS + k;
    float s = 0.f;
#pragma unroll 8
    for (int q = 0; q < NPTS; q++) s += p[(size_t)q*NPTS];
    cs[b*NPTS + k] = s;
}

// ---------------- scale xv columns (fold double-norm), rounded ----------------
__global__ void scalexv_k(float* __restrict__ xv, const float* __restrict__ cs)
{
    long i = (long)blockIdx.x*256 + threadIdx.x;       // float4 index
    if (i >= (long)BATCH*512*NPTS/4) return;
    long e = i*4;
    int k = e % NPTS;
    int b = e / ((long)512*NPTS);
    const float4 c4 = *(const float4*)(cs + b*NPTS + k);
    float4 v = ((float4*)xv)[i];
    v.x = rnd(v.x / (1e-9f + c4.x)); v.y = rnd(v.y / (1e-9f + c4.y));
    v.z = rnd(v.z / (1e-9f + c4.z)); v.w = rnd(v.w / (1e-9f + c4.w));
    ((float4*)xv)[i] = v;
}

// ---------------- hmxr[c][n] = rnd(h[c][n] - xrT[n][c]) ----------------
__global__ void tsub_k(const float* __restrict__ h, const float* __restrict__ xrT,
                       float* __restrict__ o)
{
    __shared__ float s[32][33];
    int b = blockIdx.z;
    int n0 = blockIdx.x*32, c0 = blockIdx.y*32;
    const float* xb = xrT + (long)b*NPTS*512;
    const float* hb = h + (long)b*512*NPTS;
    float*       ob = o + (long)b*512*NPTS;
    int x = threadIdx.x, y = threadIdx.y;
#pragma unroll
    for (int i = 0; i < 4; i++)
        s[y+8*i][x] = xb[(long)(n0+y+8*i)*512 + c0+x];
    __syncthreads();
#pragma unroll
    for (int i = 0; i < 4; i++) {
        int c = c0 + y + 8*i;
        long off = (long)c*NPTS + n0 + x;
        ob[off] = rnd(hb[off] - s[x][y+8*i]);
    }
}

// ---------------- BN batch stats per channel ----------------
__global__ void bnstats_k(const float* __restrict__ d)
{
    int c = blockIdx.x;
    int t = threadIdx.x;
    double s = 0.0, s2 = 0.0;
    for (int i = t; i < BATCH*NPTS; i += 256) {
        int b = i / NPTS, n = i % NPTS;
        float v = d[((long)b*512 + c)*NPTS + n];
        s += v; s2 += (double)v*v;
    }
    __shared__ double sh[256], sh2[256];
    sh[t] = s; sh2[t] = s2; __syncthreads();
    for (int o = 128; o > 0; o >>= 1) {
        if (t < o) { sh[t] += sh[t+o]; sh2[t] += sh2[t+o]; }
        __syncthreads();
    }
    if (t == 0) {
        double mu  = sh[0]  / (double)(BATCH*NPTS);
        double var = sh2[0] / (double)(BATCH*NPTS) - mu*mu;
        g_mu[c] = (float)mu;
        g_rs[c] = (float)(1.0 / sqrt(var + 1e-5));
    }
}

// ---------------- h2 = rnd(h + relu(bn(d))) ----------------
__global__ void bnapply_k(const float* __restrict__ h, const float* __restrict__ d,
                          const float* __restrict__ gamma, const float* __restrict__ beta,
                          float* __restrict__ h2)
{
    long idx = (long)blockIdx.x*blockDim.x + threadIdx.x;
    if (idx >= (long)BATCH*512*NPTS) return;
    int c = (idx / NPTS) % 512;
    float v = gamma[c] * (d[idx] - g_mu[c]) * g_rs[c] + beta[c];
    h2[idx] = rnd(h[idx] + fmaxf(v, 0.f));
}

// ---------------- launch ----------------
extern "C" void kernel_launch(void* const* d_in, const int* in_sizes, int n_in,
                              void* d_out, int out_size)
{
    const float* x    = (const float*)d_in[0];
    const float* w1   = (const float*)d_in[1];
    const float* b1   = (const float*)d_in[2];
    const float* w2   = (const float*)d_in[3];
    const float* b2   = (const float*)d_in[4];
    const float* w3   = (const float*)d_in[5];
    const float* b3   = (const float*)d_in[6];
    const float* w4   = (const float*)d_in[7];
    const float* b4   = (const float*)d_in[8];
    const float* wqk  = (const float*)d_in[9];
    const float* wv   = (const float*)d_in[10];
    const float* bv   = (const float*)d_in[11];
    const float* wt   = (const float*)d_in[12];
    const float* bt   = (const float*)d_in[13];
    const float* gamma= (const float*)d_in[14];
    const float* beta = (const float*)d_in[15];
    float* out = (float*)d_out;

    static bool attr_set = false;
    if (!attr_set) {
        cudaFuncSetAttribute(mm_tc<0,0>, cudaFuncAttributeMaxDynamicSharedMemorySize, SMEM_BYTES);
        cudaFuncSetAttribute(mm_tc<0,1>, cudaFuncAttributeMaxDynamicSharedMemorySize, SMEM_BYTES);
        cudaFuncSetAttribute(mm_tc<1,0>, cudaFuncAttributeMaxDynamicSharedMemorySize, SMEM_BYTES);
        cudaFuncSetAttribute(mm_tc<1,1>, cudaFuncAttributeMaxDynamicSharedMemorySize, SMEM_BYTES);
        attr_set = true;
    }

    float *h24,*w1p,*w2r,*w3r,*w4r,*wqkr,*wvr,*wtr;
    float *h128,*gm,*hcat,*h,*qk,*qkT,*xv,*attn,*cs,*xrT,*hmxr,*dd,*h2,*opre;
    cudaGetSymbolAddress((void**)&h24,  g_h24);
    cudaGetSymbolAddress((void**)&w1p,  g_w1p);
    cudaGetSymbolAddress((void**)&w2r,  g_w2r);
    cudaGetSymbolAddress((void**)&w3r,  g_w3r);
    cudaGetSymbolAddress((void**)&w4r,  g_w4r);
    cudaGetSymbolAddress((void**)&wqkr, g_wqkr);
    cudaGetSymbolAddress((void**)&wvr,  g_wvr);
    cudaGetSymbolAddress((void**)&wtr,  g_wtr);
    cudaGetSymbolAddress((void**)&h128, g_h128);
    cudaGetSymbolAddress((void**)&gm,   g_gm);
    cudaGetSymbolAddress((void**)&hcat, g_hcat);
    cudaGetSymbolAddress((void**)&h,    g_h);
    cudaGetSymbolAddress((void**)&qk,   g_qk);
    cudaGetSymbolAddress((void**)&qkT,  g_qkT);
    cudaGetSymbolAddress((void**)&xv,   g_xv);
    cudaGetSymbolAddress((void**)&attn, g_attn);
    cudaGetSymbolAddress((void**)&cs,   g_cs);
    cudaGetSymbolAddress((void**)&xrT,  g_xrT);
    cudaGetSymbolAddress((void**)&hmxr, g_hmxr);
    cudaGetSymbolAddress((void**)&dd,   g_dd);
    cudaGetSymbolAddress((void**)&h2,   g_h2);
    cudaGetSymbolAddress((void**)&opre, g_opre);

    const long EW = (long)BATCH*512*NPTS;

    posenc_k<<<(BATCH*3*NPTS + 255)/256, 256>>>(x, h24);
    w1pad_k<<<(128*24 + 255)/256, 256>>>(w1, w1p);
    rndcopy_k<<<(256*128/4 + 255)/256, 256>>>((const float4*)w2, (float4*)w2r, 256*128/4);
    rndcopy_k<<<(512*512/4 + 255)/256, 256>>>((const float4*)w3, (float4*)w3r, 512*512/4);
    rndcopy_k<<<(1024*512/4 + 255)/256, 256>>>((const float4*)w4, (float4*)w4r, 1024*512/4);
    rndcopy_k<<<(128*512/4 + 255)/256, 256>>>((const float4*)wqk, (float4*)wqkr, 128*512/4);
    rndcopy_k<<<(512*512/4 + 255)/256, 256>>>((const float4*)wv, (float4*)wvr, 512*512/4);
    rndcopy_k<<<(512*512/4 + 255)/256, 256>>>((const float4*)wt, (float4*)wtr, 512*512/4);

    // conv1 (24->128) + relu, rounded out
    mm_tc<0,1><<<dim3(16,1,BATCH),256,SMEM_BYTES>>>(w1p, h24, b1, h128, 128, NPTS, 24,
        0, (long)24*NPTS, (long)128*NPTS, 1, 0);
    // conv2 (128->256), rounded, writes lower half of hcat directly
    mm_tc<0,1><<<dim3(16,2,BATCH),256,SMEM_BYTES>>>(w2r, h128, b2, hcat, 256, NPTS, 128,
        0, (long)128*NPTS, (long)512*NPTS, 0, 0);
    rowmax256_k<<<BATCH*256, 256>>>(hcat, gm);
    bcast_k<<<(int)(((long)BATCH*256*NPTS + 255)/256), 256>>>(gm, hcat);
    // conv3 (512->512) + relu -> h (fp32, NOT rounded: residual path)
    mm_tc<0,0><<<dim3(16,4,BATCH),256,SMEM_BYTES>>>(w3r, hcat, b3, h, 512, NPTS, 512,
        0, (long)512*NPTS, (long)512*NPTS, 1, 0);
    // q/k projection (tied weights), B=h needs cvt, rounded out
    mm_tc<1,1><<<dim3(16,1,BATCH),256,SMEM_BYTES>>>(wqkr, h, nullptr, qk, 128, NPTS, 512,
        0, (long)512*NPTS, (long)128*NPTS, 0, 0);
    tqk_k<<<dim3(NPTS/32, 4, BATCH), dim3(32,8)>>>(qk, qkT);
    // v projection, B=h needs cvt (out scaled+rounded later)
    mm_tc<1,0><<<dim3(16,4,BATCH),256,SMEM_BYTES>>>(wvr, h, bv, xv, 512, NPTS, 512,
        0, (long)512*NPTS, (long)512*NPTS, 0, 0);
    // energy = qkT @ qk
    mm_tc<0,0><<<dim3(16,16,BATCH),256,SMEM_BYTES>>>(qkT, qk, nullptr, attn, NPTS, NPTS, 128,
        (long)NPTS*128, (long)128*NPTS, (long)NPTS*NPTS, 0, 0);
    softmax_k<<<BATCH*NPTS, 256>>>(attn);
    colsum_k<<<dim3(NPTS/256, BATCH), 256>>>(attn, cs);
    scalexv_k<<<(int)((EW/4 + 255)/256), 256>>>(xv, cs);
    // x_r^T = attn @ xv^T (both pre-rounded)
    mm_tc<0,0><<<dim3(4,16,BATCH),256,SMEM_BYTES>>>(attn, xv, nullptr, xrT, NPTS, 512, NPTS,
        (long)NPTS*NPTS, (long)512*NPTS, (long)NPTS*512, 0, 1);
    tsub_k<<<dim3(NPTS/32, 16, BATCH), dim3(32,8)>>>(h, xrT, hmxr);
    // d = wt @ (h - x_r) + bt
    mm_tc<0,0><<<dim3(16,4,BATCH),256,SMEM_BYTES>>>(wtr, hmxr, bt, dd, 512, NPTS, 512,
        0, (long)512*NPTS, (long)512*NPTS, 0, 0);
    bnstats_k<<<512, 256>>>(dd);
    bnapply_k<<<(int)((EW + 255)/256), 256>>>(h, dd, gamma, beta, h2);
    // conv4 (512->1024)
    mm_tc<0,0><<<dim3(16,8,BATCH),256,SMEM_BYTES>>>(w4r, h2, b4, opre, 1024, NPTS, 512,
        0, (long)512*NPTS, (long)1024*NPTS, 0, 0);
    rowmax_k<<<BATCH*1024, 256>>>(opre, out);
}